// round 7
// baseline (speedup 1.0000x reference)
#include <cuda_runtime.h>
#include <cuda_fp16.h>
#include <stdint.h>
#include <math.h>

#define N      8192
#define FIN    256
#define FOUT   128
#define MT     128
#define KC     64
#define KSLICE 4096
#define NC     64

// smem layout (bytes)
#define OFF_EP  0
#define OFF_EN  16384
#define OFF_A   32768            // 1 x 18432
#define B_STG   18432
#define OFF_B   51200            // 3 stages -> 106496
#define ADJ_STG 34816            // 128 x 272
#define OFF_ADJ 106496           // 2 stages -> 176128
#define OFF_WF  176128           // fp16 w tile for FFMA chunk
#define OFF_BF  194560           // fp16 B tile for FFMA chunk
#define SMEM_TOTAL 212992

__device__ float g_Wh[(size_t)N * FOUT];
__device__ __half g_WhT[(size_t)FOUT * N];
__device__ float g_s1[N], g_s2[N];
__device__ float g_E2p[N], g_E2n[N];
__device__ float4 g_rc4[N];          // {-s1, r1p, r1n, 0}
__device__ float g_part[2][(size_t)N * FOUT];
__device__ float g_partf[2][(size_t)N * FOUT];
__device__ float g_Zpart[2][N];

__device__ __forceinline__ uint32_t smem_u32(const void* p) {
    uint32_t a;
    asm("{ .reg .u64 t; cvta.to.shared.u64 t, %1; cvt.u32.u64 %0, t; }" : "=r"(a) : "l"(p));
    return a;
}
__device__ __forceinline__ void cpa16(uint32_t s, const void* g) {
    asm volatile("cp.async.cg.shared.global [%0], [%1], 16;" :: "r"(s), "l"(g));
}
#define CP_COMMIT() asm volatile("cp.async.commit_group;" ::: "memory")
#define CP_WAIT0()  asm volatile("cp.async.wait_group 0;" ::: "memory")
#define CP_WAIT1()  asm volatile("cp.async.wait_group 1;" ::: "memory")

__device__ __forceinline__ void ldsm4(uint32_t* r, uint32_t addr) {
    asm volatile("ldmatrix.sync.aligned.m8n8.x4.shared.b16 {%0,%1,%2,%3}, [%4];"
        : "=r"(r[0]), "=r"(r[1]), "=r"(r[2]), "=r"(r[3]) : "r"(addr));
}
__device__ __forceinline__ void mma16816(float* d, const uint32_t* a, const uint32_t* b) {
    asm volatile("mma.sync.aligned.m16n8k16.row.col.f32.f16.f16.f32 "
        "{%0,%1,%2,%3}, {%4,%5,%6,%7}, {%8,%9}, {%0,%1,%2,%3};"
        : "+f"(d[0]), "+f"(d[1]), "+f"(d[2]), "+f"(d[3])
        : "r"(a[0]), "r"(a[1]), "r"(a[2]), "r"(a[3]), "r"(b[0]), "r"(b[1]));
}

// ---- Wh = h @ W^T (fp32) + transposed fp16 copy ----
__global__ void __launch_bounds__(128) k_wh(const float* __restrict__ h,
                                            const float* __restrict__ W) {
    __shared__ float hs[32][FIN];
    const int row0 = blockIdx.x * 32, t = threadIdx.x;
    const float4* h4 = (const float4*)(h + (size_t)row0 * FIN);
    float4* hs4 = (float4*)&hs[0][0];
    #pragma unroll
    for (int u = 0; u < 16; u++) hs4[t + u * 128] = h4[t + u * 128];
    __syncthreads();
    const float4* W4 = (const float4*)(W + (size_t)t * FIN);
    float acc[32];
    #pragma unroll
    for (int r = 0; r < 32; r++) acc[r] = 0.f;
    for (int k0 = 0; k0 < FIN; k0 += 32) {
        float4 wv[8];
        #pragma unroll
        for (int c = 0; c < 8; c++) wv[c] = W4[k0 / 4 + c];
        #pragma unroll
        for (int r = 0; r < 32; r++) {
            const float4* hv4 = (const float4*)&hs[r][k0];
            #pragma unroll
            for (int c = 0; c < 8; c++) {
                float4 hv = hv4[c];
                acc[r] += hv.x * wv[c].x; acc[r] += hv.y * wv[c].y;
                acc[r] += hv.z * wv[c].z; acc[r] += hv.w * wv[c].w;
            }
        }
    }
    #pragma unroll
    for (int r = 0; r < 32; r++) {
        g_Wh[(size_t)(row0 + r) * FOUT + t] = acc[r];
        g_WhT[(size_t)t * N + row0 + r] = __float2half_rn(acc[r]);
    }
}

__global__ void __launch_bounds__(256) k_s12(const float* __restrict__ a1,
                                             const float* __restrict__ a2) {
    const int gw = (blockIdx.x * 256 + threadIdx.x) >> 5, lane = threadIdx.x & 31;
    const float* whr = g_Wh + (size_t)gw * FOUT;
    float p1 = 0.f, p2 = 0.f;
    #pragma unroll
    for (int c = 0; c < 4; c++) {
        float v = whr[lane + 32 * c];
        p1 += v * __ldg(&a1[lane + 32 * c]);
        p2 += v * __ldg(&a2[lane + 32 * c]);
    }
    #pragma unroll
    for (int o = 16; o > 0; o >>= 1) {
        p1 += __shfl_xor_sync(~0u, p1, o); p2 += __shfl_xor_sync(~0u, p2, o);
    }
    if (lane == 0) { g_s1[gw] = p1; g_s2[gw] = p2; }
}

// fused: s2max reduce + per-row shifted factors (single block)
__global__ void __launch_bounds__(1024) k_fact() {
    __shared__ float red[1024];
    const int t = threadIdx.x;
    float m = -1e30f;
    #pragma unroll
    for (int u = 0; u < 8; u++) m = fmaxf(m, g_s2[t + u * 1024]);
    red[t] = m; __syncthreads();
    for (int s = 512; s > 0; s >>= 1) {
        if (t < s) red[t] = fmaxf(red[t], red[t + s]);
        __syncthreads();
    }
    const float s2max = red[0];
    #pragma unroll
    for (int u = 0; u < 8; u++) {
        const int i = t + u * 1024;
        const float s1 = g_s1[i], s2 = g_s2[i];
        const float tt = s1 + s2max;
        const float c = (tt > 0.f ? tt : 0.2f * tt) - 6.9314718f;
        g_rc4[i] = make_float4(-s1, expf(s1 - c), expf(0.2f * s1 - c), 0.f);
        g_E2p[i] = expf(s2);
        g_E2n[i] = expf(0.2f * s2);
    }
}

// ---- fused masked-softmax attention GEMM: HMMA + interleaved FFMA offload ----
__global__ void __launch_bounds__(256, 1) k_attn(const int* __restrict__ adj) {
    extern __shared__ char smem[];
    const uint32_t sb = smem_u32(smem);
    const int t = threadIdx.x, wid = t >> 5, lane = t & 31;
    const int mt_ = blockIdx.x >> 1, slice = blockIdx.x & 1;
    const int row0 = mt_ * MT, jbase = slice * KSLICE;

    auto fill_adj = [&](int c, int s) {
        const size_t gcol = (size_t)jbase + (size_t)c * KC;
        #pragma unroll
        for (int k = 0; k < 8; k++) {
            const int id = t + k * 256;
            const int r = id >> 4, cc = id & 15;
            cpa16(sb + OFF_ADJ + s * ADJ_STG + r * 272 + cc * 16,
                  adj + (size_t)(row0 + r) * N + gcol + cc * 4);
        }
    };
    auto fill_B = [&](int c, int s) {
        const size_t gcol = (size_t)jbase + (size_t)c * KC;
        #pragma unroll
        for (int k = 0; k < 4; k++) {
            const int id = t + k * 256;
            const int f = id >> 3, cc = id & 7;
            cpa16(sb + OFF_B + s * B_STG + f * 144 + cc * 16,
                  g_WhT + (size_t)f * N + gcol + cc * 8);
        }
    };

    // gen mapping: one row per thread pair, 32 j's each
    const int m = t >> 1, jh = (t & 1) * 32;
    const float4 rc = __ldg(&g_rc4[row0 + m]);     // {-s1, r1p, r1n}
    const float eth = expf(rc.x);                  // exp(-s1): s2>=-s1 <=> E2p>=eth
    float zacc = 0.f;

    // prologue: factors + stages 0,1
    {
        #pragma unroll
        for (int k = 0; k < 4; k++) {
            const int ch = t + k * 256;
            cpa16(sb + OFF_EP + ch * 16, g_E2p + jbase + ch * 4);
            cpa16(sb + OFF_EN + ch * 16, g_E2n + jbase + ch * 4);
        }
        fill_adj(0, 0); fill_B(0, 0); CP_COMMIT();
        fill_adj(1, 1); fill_B(1, 1); CP_COMMIT();
    }

    // tensor mapping: 8 warps = 4x2, warp tile 32 x 64
    const int r0 = (wid >> 1) * 32, c0 = (wid & 1) * 64;
    const uint32_t aB = sb + OFF_A + (r0 + (lane & 15)) * 144 + (lane >> 4) * 16;
    const uint32_t bOff = (uint32_t)((c0 + (lane & 7) + ((lane >> 4) & 1) * 8) * 144
                                     + ((lane >> 3) & 1) * 16);
    float acc[2][8][4];
    #pragma unroll
    for (int i = 0; i < 2; i++)
        #pragma unroll
        for (int j = 0; j < 8; j++)
            #pragma unroll
            for (int q = 0; q < 4; q++) acc[i][j][q] = 0.f;

    // FFMA offload state: 16x16 thread grid, 8x8 cells each
    const int frg = (t >> 4) * 8, fcg = (t & 15) * 8;
    float acc_f[8][8];
    #pragma unroll
    for (int i = 0; i < 8; i++)
        #pragma unroll
        for (int j = 0; j < 8; j++) acc_f[i][j] = 0.f;
    int kf = 64;   // inactive

    #pragma unroll 1
    for (int c = 0; c < NC; c++) {
        const bool isF = ((c & 7) == 7);
        CP_WAIT1();
        __syncthreads();

        // ---- gen chunk c (fp16 w tile -> A or WF) ----
        {
            const int sA = c & 1;
            const int4* ar = (const int4*)(smem + OFF_ADJ + sA * ADJ_STG + m * 272 + jh * 4);
            const float4* epp = (const float4*)(smem + OFF_EP + (c * KC + jh) * 4);
            const float4* enp = (const float4*)(smem + OFF_EN + (c * KC + jh) * 4);
            uint32_t v[16];
            #pragma unroll
            for (int u = 0; u < 8; u++) {
                const int4 a4 = ar[u];
                const float4 ep = epp[u], en = enp[u];
                float w0 = (ep.x >= eth) ? rc.y * ep.x : rc.z * en.x; if (a4.x == 0) w0 = 0.f;
                float w1 = (ep.y >= eth) ? rc.y * ep.y : rc.z * en.y; if (a4.y == 0) w1 = 0.f;
                float w2 = (ep.z >= eth) ? rc.y * ep.z : rc.z * en.z; if (a4.z == 0) w2 = 0.f;
                float w3 = (ep.w >= eth) ? rc.y * ep.w : rc.z * en.w; if (a4.w == 0) w3 = 0.f;
                zacc += (w0 + w1) + (w2 + w3);
                __half2 p0 = __floats2half2_rn(w0, w1), p1 = __floats2half2_rn(w2, w3);
                v[2 * u] = *(uint32_t*)&p0; v[2 * u + 1] = *(uint32_t*)&p1;
            }
            uint4* dst = (uint4*)(smem + (isF ? OFF_WF : OFF_A) + m * 144 + jh * 2);
            dst[0] = make_uint4(v[0], v[1], v[2], v[3]);
            dst[1] = make_uint4(v[4], v[5], v[6], v[7]);
            dst[2] = make_uint4(v[8], v[9], v[10], v[11]);
            dst[3] = make_uint4(v[12], v[13], v[14], v[15]);
        }
        __syncthreads();

        if (c + 2 < NC) { fill_adj(c + 2, c & 1); fill_B(c + 2, (c + 2) % 3); }
        CP_COMMIT();

        // ---- FFMA substep: up to 10 k-steps of pending offload chunk ----
        if (kf < 64) {
            #pragma unroll
            for (int kp = 0; kp < 5; kp++) {
                const int k = kf + kp * 2;
                if (k < 64) {
                    float2 wv[8], bv[8];
                    #pragma unroll
                    for (int rr = 0; rr < 8; rr++)
                        wv[rr] = __half22float2(
                            *(const __half2*)(smem + OFF_WF + (frg + rr) * 144 + k * 2));
                    #pragma unroll
                    for (int cc = 0; cc < 8; cc++)
                        bv[cc] = __half22float2(
                            *(const __half2*)(smem + OFF_BF + (fcg + cc) * 144 + k * 2));
                    #pragma unroll
                    for (int rr = 0; rr < 8; rr++)
                        #pragma unroll
                        for (int cc = 0; cc < 8; cc++)
                            acc_f[rr][cc] += wv[rr].x * bv[cc].x + wv[rr].y * bv[cc].y;
                }
            }
            kf += 10;
        }

        if (isF) {
            // activate offload chunk: copy B(c) stage -> BF; w already in WF
            const uint4* src = (const uint4*)(smem + OFF_B + (c % 3) * B_STG);
            uint4* dst = (uint4*)(smem + OFF_BF);
            #pragma unroll
            for (int q = 0; q < 5; q++) {
                const int idx = t + q * 256;
                if (idx < 1152) dst[idx] = src[idx];
            }
            kf = 0;
        } else {
            // ---- tensor mma chunk c ----
            const uint32_t bB = sb + OFF_B + (c % 3) * B_STG + bOff;
            #pragma unroll
            for (int kk = 0; kk < 4; kk++) {
                uint32_t a[2][4];
                ldsm4(a[0], aB + kk * 32);
                ldsm4(a[1], aB + 16 * 144 + kk * 32);
                #pragma unroll
                for (int ng = 0; ng < 4; ng++) {
                    uint32_t b[4];
                    ldsm4(b, bB + ng * 16 * 144 + kk * 32);
                    #pragma unroll
                    for (int mi = 0; mi < 2; mi++) {
                        mma16816(acc[mi][2 * ng], a[mi], b);
                        mma16816(acc[mi][2 * ng + 1], a[mi], b + 2);
                    }
                }
            }
        }
    }

    // flush remaining offload k-steps (chunk 63)
    __syncthreads();
    while (kf < 64) {
        #pragma unroll
        for (int kp = 0; kp < 5; kp++) {
            const int k = kf + kp * 2;
            if (k < 64) {
                float2 wv[8], bv[8];
                #pragma unroll
                for (int rr = 0; rr < 8; rr++)
                    wv[rr] = __half22float2(
                        *(const __half2*)(smem + OFF_WF + (frg + rr) * 144 + k * 2));
                #pragma unroll
                for (int cc = 0; cc < 8; cc++)
                    bv[cc] = __half22float2(
                        *(const __half2*)(smem + OFF_BF + (fcg + cc) * 144 + k * 2));
                #pragma unroll
                for (int rr = 0; rr < 8; rr++)
                    #pragma unroll
                    for (int cc = 0; cc < 8; cc++)
                        acc_f[rr][cc] += wv[rr].x * bv[cc].x + wv[rr].y * bv[cc].y;
            }
        }
        kf += 10;
    }

    // Z reduce (threads t, t^1 share row)
    zacc += __shfl_xor_sync(~0u, zacc, 1);
    if ((t & 1) == 0) g_Zpart[slice][row0 + m] = zacc;

    // epilogue: tensor accs
    const int quad = lane >> 2, qc = (lane & 3) * 2;
    #pragma unroll
    for (int mi = 0; mi < 2; mi++) {
        const int rg = row0 + r0 + mi * 16 + quad;
        #pragma unroll
        for (int nt = 0; nt < 8; nt++) {
            const int col = c0 + nt * 8 + qc;
            float* p = g_part[slice] + (size_t)rg * FOUT + col;
            *(float2*)p = make_float2(acc[mi][nt][0], acc[mi][nt][1]);
            *(float2*)(p + 8 * FOUT) = make_float2(acc[mi][nt][2], acc[mi][nt][3]);
        }
    }
    // epilogue: FFMA accs
    #pragma unroll
    for (int rr = 0; rr < 8; rr++) {
        float* p = g_partf[slice] + (size_t)(row0 + frg + rr) * FOUT + fcg;
        *(float4*)p = make_float4(acc_f[rr][0], acc_f[rr][1], acc_f[rr][2], acc_f[rr][3]);
        *(float4*)(p + 4) = make_float4(acc_f[rr][4], acc_f[rr][5], acc_f[rr][6], acc_f[rr][7]);
    }
}

// combine: out = elu((p0+p1+pf0+pf1)/(z0+z1))
__global__ void __launch_bounds__(256) k_final(float* __restrict__ out) {
    const int idx = blockIdx.x * 256 + threadIdx.x;
    const int row = idx >> 5, c4 = (idx & 31) * 4;
    const size_t off = (size_t)row * FOUT + c4;
    const float4 p0 = *(const float4*)(g_part[0] + off);
    const float4 p1 = *(const float4*)(g_part[1] + off);
    const float4 q0 = *(const float4*)(g_partf[0] + off);
    const float4 q1 = *(const float4*)(g_partf[1] + off);
    const float inv = 1.0f / (g_Zpart[0][row] + g_Zpart[1][row]);
    float4 o; float v;
    v = (p0.x + p1.x + q0.x + q1.x) * inv; o.x = v > 0.f ? v : expm1f(v);
    v = (p0.y + p1.y + q0.y + q1.y) * inv; o.y = v > 0.f ? v : expm1f(v);
    v = (p0.z + p1.z + q0.z + q1.z) * inv; o.z = v > 0.f ? v : expm1f(v);
    v = (p0.w + p1.w + q0.w + q1.w) * inv; o.w = v > 0.f ? v : expm1f(v);
    *(float4*)(out + off) = o;
}

extern "C" void kernel_launch(void* const* d_in, const int* in_sizes, int n_in,
                              void* d_out, int out_size) {
    const float* h   = (const float*)d_in[0];
    const int*   adj = (const int*)d_in[1];
    const float* W   = (const float*)d_in[2];
    const float* a1  = (const float*)d_in[3];
    const float* a2  = (const float*)d_in[4];
    float* out = (float*)d_out;

    cudaFuncSetAttribute(k_attn, cudaFuncAttributeMaxDynamicSharedMemorySize, SMEM_TOTAL);

    k_wh   <<<N / 32, 128>>>(h, W);
    k_s12  <<<N / 8, 256>>>(a1, a2);
    k_fact <<<1, 1024>>>();
    k_attn <<<128, 256, SMEM_TOTAL>>>(adj);
    k_final<<<N * FOUT / 1024, 256>>>(out);
}

// round 8
// speedup vs baseline: 1.8593x; 1.8593x over previous
#include <cuda_runtime.h>
#include <cuda_fp16.h>
#include <stdint.h>
#include <math.h>

#define N      8192
#define FIN    256
#define FOUT   128
#define MT     128
#define KC     64
#define KSLICE 4096
#define NC     64

// smem layout (bytes)
#define OFF_EP  0
#define OFF_EN  16384
#define ADJ_STG 34816            // 128 x 272
#define OFF_ADJ 32768            // 3 stages -> 137216
#define B_STG   18432            // 128 x 144
#define OFF_B   137216           // 3 stages -> 192512
#define OFF_A   192512           // 18432
#define SMEM_TOTAL 210944

__device__ float g_Wh[(size_t)N * FOUT];
__device__ __half g_WhT[(size_t)FOUT * N];
__device__ float g_s1[N], g_s2[N];
__device__ float g_E2p[N], g_E2n[N];
__device__ float4 g_rc4[N];          // {-s1, r1p, r1n, 0}
__device__ float g_part[2][(size_t)N * FOUT];
__device__ float g_Zpart[2][N];

__device__ __forceinline__ uint32_t smem_u32(const void* p) {
    uint32_t a;
    asm("{ .reg .u64 t; cvta.to.shared.u64 t, %1; cvt.u32.u64 %0, t; }" : "=r"(a) : "l"(p));
    return a;
}
__device__ __forceinline__ void cpa16(uint32_t s, const void* g) {
    asm volatile("cp.async.cg.shared.global [%0], [%1], 16;" :: "r"(s), "l"(g));
}
#define CP_COMMIT() asm volatile("cp.async.commit_group;" ::: "memory")
#define CP_WAIT1()  asm volatile("cp.async.wait_group 1;" ::: "memory")

__device__ __forceinline__ void ldsm4(uint32_t* r, uint32_t addr) {
    asm volatile("ldmatrix.sync.aligned.m8n8.x4.shared.b16 {%0,%1,%2,%3}, [%4];"
        : "=r"(r[0]), "=r"(r[1]), "=r"(r[2]), "=r"(r[3]) : "r"(addr));
}
__device__ __forceinline__ void mma16816(float* d, const uint32_t* a, const uint32_t* b) {
    asm volatile("mma.sync.aligned.m16n8k16.row.col.f32.f16.f16.f32 "
        "{%0,%1,%2,%3}, {%4,%5,%6,%7}, {%8,%9}, {%0,%1,%2,%3};"
        : "+f"(d[0]), "+f"(d[1]), "+f"(d[2]), "+f"(d[3])
        : "r"(a[0]), "r"(a[1]), "r"(a[2]), "r"(a[3]), "r"(b[0]), "r"(b[1]));
}

// ---- Wh = h @ W^T (fp32) + transposed fp16 copy ----
__global__ void __launch_bounds__(128) k_wh(const float* __restrict__ h,
                                            const float* __restrict__ W) {
    __shared__ float hs[32][FIN];
    const int row0 = blockIdx.x * 32, t = threadIdx.x;
    const float4* h4 = (const float4*)(h + (size_t)row0 * FIN);
    float4* hs4 = (float4*)&hs[0][0];
    #pragma unroll
    for (int u = 0; u < 16; u++) hs4[t + u * 128] = h4[t + u * 128];
    __syncthreads();
    const float4* W4 = (const float4*)(W + (size_t)t * FIN);
    float acc[32];
    #pragma unroll
    for (int r = 0; r < 32; r++) acc[r] = 0.f;
    for (int k0 = 0; k0 < FIN; k0 += 32) {
        float4 wv[8];
        #pragma unroll
        for (int c = 0; c < 8; c++) wv[c] = W4[k0 / 4 + c];
        #pragma unroll
        for (int r = 0; r < 32; r++) {
            const float4* hv4 = (const float4*)&hs[r][k0];
            #pragma unroll
            for (int c = 0; c < 8; c++) {
                float4 hv = hv4[c];
                acc[r] += hv.x * wv[c].x; acc[r] += hv.y * wv[c].y;
                acc[r] += hv.z * wv[c].z; acc[r] += hv.w * wv[c].w;
            }
        }
    }
    #pragma unroll
    for (int r = 0; r < 32; r++) {
        g_Wh[(size_t)(row0 + r) * FOUT + t] = acc[r];
        g_WhT[(size_t)t * N + row0 + r] = __float2half_rn(acc[r]);
    }
}

__global__ void __launch_bounds__(256) k_s12(const float* __restrict__ a1,
                                             const float* __restrict__ a2) {
    const int gw = (blockIdx.x * 256 + threadIdx.x) >> 5, lane = threadIdx.x & 31;
    const float* whr = g_Wh + (size_t)gw * FOUT;
    float p1 = 0.f, p2 = 0.f;
    #pragma unroll
    for (int c = 0; c < 4; c++) {
        float v = whr[lane + 32 * c];
        p1 += v * __ldg(&a1[lane + 32 * c]);
        p2 += v * __ldg(&a2[lane + 32 * c]);
    }
    #pragma unroll
    for (int o = 16; o > 0; o >>= 1) {
        p1 += __shfl_xor_sync(~0u, p1, o); p2 += __shfl_xor_sync(~0u, p2, o);
    }
    if (lane == 0) { g_s1[gw] = p1; g_s2[gw] = p2; }
}

// fused: s2max reduce + per-row shifted factors (single block)
__global__ void __launch_bounds__(1024) k_fact() {
    __shared__ float red[1024];
    const int t = threadIdx.x;
    float m = -1e30f;
    #pragma unroll
    for (int u = 0; u < 8; u++) m = fmaxf(m, g_s2[t + u * 1024]);
    red[t] = m; __syncthreads();
    for (int s = 512; s > 0; s >>= 1) {
        if (t < s) red[t] = fmaxf(red[t], red[t + s]);
        __syncthreads();
    }
    const float s2max = red[0];
    #pragma unroll
    for (int u = 0; u < 8; u++) {
        const int i = t + u * 1024;
        const float s1 = g_s1[i], s2 = g_s2[i];
        const float tt = s1 + s2max;
        const float c = (tt > 0.f ? tt : 0.2f * tt) - 6.9314718f;
        g_rc4[i] = make_float4(-s1, expf(s1 - c), expf(0.2f * s1 - c), 0.f);
        g_E2p[i] = expf(s2);
        g_E2n[i] = expf(0.2f * s2);
    }
}

// ---- fused masked-softmax attention GEMM, 512-thread monolith ----
__global__ void __launch_bounds__(512, 1) k_attn(const int* __restrict__ adj) {
    extern __shared__ char smem[];
    const uint32_t sb = smem_u32(smem);
    const int t = threadIdx.x, wid = t >> 5, lane = t & 31;
    const int mt_ = blockIdx.x >> 1, slice = blockIdx.x & 1;
    const int row0 = mt_ * MT, jbase = slice * KSLICE;

    auto fill_adj = [&](int c, int s) {
        const size_t gcol = (size_t)jbase + (size_t)c * KC;
        #pragma unroll
        for (int k = 0; k < 4; k++) {
            const int id = t + k * 512;
            const int r = id >> 4, cc = id & 15;
            cpa16(sb + OFF_ADJ + s * ADJ_STG + r * 272 + cc * 16,
                  adj + (size_t)(row0 + r) * N + gcol + cc * 4);
        }
    };
    auto fill_B = [&](int c, int s) {
        const size_t gcol = (size_t)jbase + (size_t)c * KC;
        #pragma unroll
        for (int k = 0; k < 2; k++) {
            const int id = t + k * 512;
            const int f = id >> 3, cc = id & 7;
            cpa16(sb + OFF_B + s * B_STG + f * 144 + cc * 16,
                  g_WhT + (size_t)f * N + gcol + cc * 8);
        }
    };

    // gen mapping: 4 threads per row, 16 j's each
    const int m = t >> 2, jq = (t & 3) * 16;
    const float4 rc = __ldg(&g_rc4[row0 + m]);     // {-s1, r1p, r1n}
    const float eth = expf(rc.x);                  // s2>=-s1 <=> E2p>=eth
    float zacc = 0.f;

    // prologue: factors + stages 0,1
    {
        #pragma unroll
        for (int k = 0; k < 2; k++) {
            const int ch = t + k * 512;
            cpa16(sb + OFF_EP + ch * 16, g_E2p + jbase + ch * 4);
            cpa16(sb + OFF_EN + ch * 16, g_E2n + jbase + ch * 4);
        }
        fill_adj(0, 0); fill_B(0, 0); CP_COMMIT();
        fill_adj(1, 1); fill_B(1, 1); CP_COMMIT();
    }

    // mma mapping: 16 warps = 4x4, warp tile 32 x 32
    const int r0 = (wid >> 2) * 32, c0 = (wid & 3) * 32;
    const uint32_t aB = sb + OFF_A + (r0 + (lane & 15)) * 144 + (lane >> 4) * 16;
    const uint32_t bOff = (uint32_t)((c0 + (lane & 7) + ((lane >> 4) & 1) * 8) * 144
                                     + ((lane >> 3) & 1) * 16);
    float acc[2][4][4];
    #pragma unroll
    for (int i = 0; i < 2; i++)
        #pragma unroll
        for (int j = 0; j < 4; j++)
            #pragma unroll
            for (int q = 0; q < 4; q++) acc[i][j][q] = 0.f;

    #pragma unroll 1
    for (int c = 0; c < NC; c++) {
        CP_WAIT1();
        __syncthreads();

        // ---- gen chunk c: 16 w's per thread into A ----
        {
            const int s = c % 3;
            const int4* ar = (const int4*)(smem + OFF_ADJ + s * ADJ_STG + m * 272 + jq * 4);
            const float4* epp = (const float4*)(smem + OFF_EP + (c * KC + jq) * 4);
            const float4* enp = (const float4*)(smem + OFF_EN + (c * KC + jq) * 4);
            uint32_t v[8];
            #pragma unroll
            for (int u = 0; u < 4; u++) {
                const int4 a4 = ar[u];
                const float4 ep = epp[u], en = enp[u];
                float w0 = (ep.x >= eth) ? rc.y * ep.x : rc.z * en.x; if (a4.x == 0) w0 = 0.f;
                float w1 = (ep.y >= eth) ? rc.y * ep.y : rc.z * en.y; if (a4.y == 0) w1 = 0.f;
                float w2 = (ep.z >= eth) ? rc.y * ep.z : rc.z * en.z; if (a4.z == 0) w2 = 0.f;
                float w3 = (ep.w >= eth) ? rc.y * ep.w : rc.z * en.w; if (a4.w == 0) w3 = 0.f;
                zacc += (w0 + w1) + (w2 + w3);
                __half2 p0 = __floats2half2_rn(w0, w1), p1 = __floats2half2_rn(w2, w3);
                v[2 * u] = *(uint32_t*)&p0; v[2 * u + 1] = *(uint32_t*)&p1;
            }
            uint4* dst = (uint4*)(smem + OFF_A + m * 144 + jq * 2);
            dst[0] = make_uint4(v[0], v[1], v[2], v[3]);
            dst[1] = make_uint4(v[4], v[5], v[6], v[7]);
        }
        __syncthreads();

        if (c + 2 < NC) { fill_adj(c + 2, (c + 2) % 3); fill_B(c + 2, (c + 2) % 3); }
        CP_COMMIT();

        // ---- mma chunk c: warp tile 32x32 ----
        const uint32_t bB = sb + OFF_B + (c % 3) * B_STG + bOff;
        #pragma unroll
        for (int kk = 0; kk < 4; kk++) {
            uint32_t a[2][4], b[2][4];
            ldsm4(a[0], aB + kk * 32);
            ldsm4(a[1], aB + 16 * 144 + kk * 32);
            ldsm4(b[0], bB + kk * 32);
            ldsm4(b[1], bB + 16 * 144 + kk * 32);
            #pragma unroll
            for (int mi = 0; mi < 2; mi++)
                #pragma unroll
                for (int ng = 0; ng < 2; ng++) {
                    mma16816(acc[mi][2 * ng], a[mi], b[ng]);
                    mma16816(acc[mi][2 * ng + 1], a[mi], b[ng] + 2);
                }
        }
    }

    // Z reduce across 4 threads sharing a row (t&3)
    zacc += __shfl_xor_sync(~0u, zacc, 1);
    zacc += __shfl_xor_sync(~0u, zacc, 2);
    if ((t & 3) == 0) g_Zpart[slice][row0 + m] = zacc;

    // epilogue
    const int quad = lane >> 2, qc = (lane & 3) * 2;
    #pragma unroll
    for (int mi = 0; mi < 2; mi++) {
        const int rg = row0 + r0 + mi * 16 + quad;
        #pragma unroll
        for (int nt = 0; nt < 4; nt++) {
            const int col = c0 + nt * 8 + qc;
            float* p = g_part[slice] + (size_t)rg * FOUT + col;
            *(float2*)p = make_float2(acc[mi][nt][0], acc[mi][nt][1]);
            *(float2*)(p + 8 * FOUT) = make_float2(acc[mi][nt][2], acc[mi][nt][3]);
        }
    }
}

// combine K-slices: out = elu((p0+p1)/(z0+z1))
__global__ void __launch_bounds__(256) k_final(float* __restrict__ out) {
    const int idx = blockIdx.x * 256 + threadIdx.x;
    const int row = idx >> 5, c4 = (idx & 31) * 4;
    const size_t off = (size_t)row * FOUT + c4;
    const float4 p0 = *(const float4*)(g_part[0] + off);
    const float4 p1 = *(const float4*)(g_part[1] + off);
    const float inv = 1.0f / (g_Zpart[0][row] + g_Zpart[1][row]);
    float4 o; float v;
    v = (p0.x + p1.x) * inv; o.x = v > 0.f ? v : expm1f(v);
    v = (p0.y + p1.y) * inv; o.y = v > 0.f ? v : expm1f(v);
    v = (p0.z + p1.z) * inv; o.z = v > 0.f ? v : expm1f(v);
    v = (p0.w + p1.w) * inv; o.w = v > 0.f ? v : expm1f(v);
    *(float4*)(out + off) = o;
}

extern "C" void kernel_launch(void* const* d_in, const int* in_sizes, int n_in,
                              void* d_out, int out_size) {
    const float* h   = (const float*)d_in[0];
    const int*   adj = (const int*)d_in[1];
    const float* W   = (const float*)d_in[2];
    const float* a1  = (const float*)d_in[3];
    const float* a2  = (const float*)d_in[4];
    float* out = (float*)d_out;

    cudaFuncSetAttribute(k_attn, cudaFuncAttributeMaxDynamicSharedMemorySize, SMEM_TOTAL);

    k_wh   <<<N / 32, 128>>>(h, W);
    k_s12  <<<N / 8, 256>>>(a1, a2);
    k_fact <<<1, 1024>>>();
    k_attn <<<128, 512, SMEM_TOTAL>>>(adj);
    k_final<<<N * FOUT / 1024, 256>>>(out);
}